// round 1
// baseline (speedup 1.0000x reference)
#include <cuda_runtime.h>
#include <math.h>

#define DIM   512
#define NHEAD 8
#define HD    64
#define FFN   2048
#define BB    4
#define TT    2048
#define ROWS  (BB*TT)     // 8192
#define CTX   64

// ---------------- scratch (allocation-free) ----------------
__device__ float g_xn  [ROWS * DIM];       // 16 MB (reused for both norms)
__device__ float g_qkv [ROWS * 3 * DIM];   // 48 MB
__device__ float g_attn[ROWS * DIM];       // 16 MB
__device__ float g_x1  [ROWS * DIM];       // 16 MB
__device__ float g_h   [ROWS * FFN];       // 64 MB

// ---------------- RMSNorm ----------------
__global__ void __launch_bounds__(256) rmsnorm_kernel(
    const float* __restrict__ x, const float* __restrict__ w, float* __restrict__ y)
{
    int row = blockIdx.x;
    int t = threadIdx.x;
    const float* xr = x + (size_t)row * DIM;
    float v0 = xr[t], v1 = xr[t + 256];
    float s = v0 * v0 + v1 * v1;
    #pragma unroll
    for (int o = 16; o; o >>= 1) s += __shfl_xor_sync(0xffffffffu, s, o);
    __shared__ float red[8];
    if ((t & 31) == 0) red[t >> 5] = s;
    __syncthreads();
    if (t < 8) {
        float r = red[t];
        #pragma unroll
        for (int o = 4; o; o >>= 1) r += __shfl_xor_sync(0xffu, r, o);
        if (t == 0) red[0] = r;
    }
    __syncthreads();
    float inv = 1.0f / sqrtf(red[0] * (1.0f / DIM) + 1e-6f);
    float* yr = y + (size_t)row * DIM;
    yr[t]       = v0 * inv * w[t];
    yr[t + 256] = v1 * inv * w[t + 256];
}

// ---------------- SGEMM 128x128 tile, 8x8 microtile ----------------
// EPI: 0 = plain, 1 = bias + GELU(exact erf), 2 = bias + residual
template<int EPI>
__global__ void __launch_bounds__(256) sgemm_kernel(
    const float* __restrict__ A, const float* __restrict__ Bm,
    const float* __restrict__ bias, const float* __restrict__ res,
    float* __restrict__ C, int M, int N, int K)
{
    __shared__ float As[8][128];
    __shared__ float Bs[8][128];

    int tid = threadIdx.x;
    int bm = blockIdx.y, bn = blockIdx.x;
    int ty = tid >> 4, tx = tid & 15;

    float acc[8][8] = {};

    int aRow = tid >> 1, aCol = (tid & 1) * 4;
    int bRow = tid >> 5, bCol = (tid & 31) * 4;
    const float* Aptr = A + (size_t)(bm * 128 + aRow) * K + aCol;
    const float* Bptr = Bm + (size_t)bRow * N + bn * 128 + bCol;

    for (int kt = 0; kt < K; kt += 8) {
        float4 av = *(const float4*)(Aptr + kt);
        float4 bv = *(const float4*)(Bptr + (size_t)kt * N);
        As[aCol + 0][aRow] = av.x;
        As[aCol + 1][aRow] = av.y;
        As[aCol + 2][aRow] = av.z;
        As[aCol + 3][aRow] = av.w;
        *(float4*)&Bs[bRow][bCol] = bv;
        __syncthreads();
        #pragma unroll
        for (int k = 0; k < 8; k++) {
            float a[8], b[8];
            *(float4*)&a[0] = *(const float4*)&As[k][ty * 8];
            *(float4*)&a[4] = *(const float4*)&As[k][ty * 8 + 4];
            *(float4*)&b[0] = *(const float4*)&Bs[k][tx * 8];
            *(float4*)&b[4] = *(const float4*)&Bs[k][tx * 8 + 4];
            #pragma unroll
            for (int i = 0; i < 8; i++)
                #pragma unroll
                for (int j = 0; j < 8; j++)
                    acc[i][j] += a[i] * b[j];
        }
        __syncthreads();
    }

    int colb = bn * 128 + tx * 8;
    #pragma unroll
    for (int i = 0; i < 8; i++) {
        size_t row = (size_t)(bm * 128 + ty * 8 + i);
        float out[8];
        #pragma unroll
        for (int j = 0; j < 8; j++) {
            float v = acc[i][j];
            if (EPI == 1) {
                v += bias[colb + j];
                v = 0.5f * v * (1.0f + erff(v * 0.70710678118654752f));
            } else if (EPI == 2) {
                v += bias[colb + j] + res[row * N + colb + j];
            }
            out[j] = v;
        }
        float* crow = C + row * N + colb;
        *(float4*)(crow)     = *(float4*)&out[0];
        *(float4*)(crow + 4) = *(float4*)&out[4];
    }
}

// ---------------- Banded attention ----------------
// One CTA per (b, h, 64-query tile). Keys window: [q0-64, q0+127] (192 keys).
// smem layout (floats): Qs 64x68 | Ks 192x68 | Vs 192x68 | Ss 64x193
#define Q_PAD 68
#define S_PAD 193
#define SMEM_FLOATS (64*Q_PAD + 192*Q_PAD + 192*Q_PAD + 64*S_PAD)

__global__ void __launch_bounds__(256) attn_kernel(
    const float* __restrict__ qkv, float* __restrict__ out)
{
    extern __shared__ float sm[];
    float* Qs = sm;
    float* Ks = Qs + 64 * Q_PAD;
    float* Vs = Ks + 192 * Q_PAD;
    float* Ss = Vs + 192 * Q_PAD;

    int tid = threadIdx.x;
    int qt = blockIdx.x, h = blockIdx.y, b = blockIdx.z;
    int q0 = qt * 64;
    int kbase = q0 - CTX;

    // load Q tile (64 rows x 64 dims)
    for (int idx = tid; idx < 64 * 16; idx += 256) {
        int r = idx >> 4, d4 = idx & 15;
        float4 v = *(const float4*)(qkv + ((size_t)(b * TT + q0 + r)) * (3 * DIM) + h * HD + d4 * 4);
        *(float4*)&Qs[r * Q_PAD + d4 * 4] = v;
    }
    // load K,V tiles (192 rows)
    for (int idx = tid; idx < 192 * 16; idx += 256) {
        int r = idx >> 4, d4 = idx & 15;
        int kg = kbase + r;
        float4 kv = {0.f, 0.f, 0.f, 0.f}, vv = {0.f, 0.f, 0.f, 0.f};
        if (kg >= 0 && kg < TT) {
            const float* base = qkv + ((size_t)(b * TT + kg)) * (3 * DIM) + h * HD + d4 * 4;
            kv = *(const float4*)(base + DIM);
            vv = *(const float4*)(base + 2 * DIM);
        }
        *(float4*)&Ks[r * Q_PAD + d4 * 4] = kv;
        *(float4*)&Vs[r * Q_PAD + d4 * 4] = vv;
    }
    __syncthreads();

    // scores
    const float scale = 0.125f;   // 1/sqrt(64)
    for (int idx = tid; idx < 64 * 192; idx += 256) {
        int q = idx / 192, kk = idx - q * 192;
        int kg = kbase + kk;
        float s = -1e30f;
        if (kk >= q && kk <= q + 2 * CTX && kg >= 0 && kg < TT) {
            const float4* qp = (const float4*)&Qs[q * Q_PAD];
            const float4* kp = (const float4*)&Ks[kk * Q_PAD];
            float a0 = 0.f;
            #pragma unroll
            for (int d = 0; d < 16; d++) {
                float4 a = qp[d], c = kp[d];
                a0 += a.x * c.x + a.y * c.y + a.z * c.z + a.w * c.w;
            }
            s = a0 * scale;
        }
        Ss[q * S_PAD + kk] = s;
    }
    __syncthreads();

    // softmax: 4 threads per query row (lanes within same warp)
    {
        int q = tid >> 2, l = tid & 3;
        float mx = -1e30f;
        for (int kk = l; kk < 192; kk += 4) mx = fmaxf(mx, Ss[q * S_PAD + kk]);
        mx = fmaxf(mx, __shfl_xor_sync(0xffffffffu, mx, 1));
        mx = fmaxf(mx, __shfl_xor_sync(0xffffffffu, mx, 2));
        float sum = 0.f;
        for (int kk = l; kk < 192; kk += 4) {
            float s = Ss[q * S_PAD + kk];
            float e = (s > -1e29f) ? expf(s - mx) : 0.f;
            Ss[q * S_PAD + kk] = e;
            sum += e;
        }
        sum += __shfl_xor_sync(0xffffffffu, sum, 1);
        sum += __shfl_xor_sync(0xffffffffu, sum, 2);
        float inv = 1.f / sum;
        for (int kk = l; kk < 192; kk += 4) Ss[q * S_PAD + kk] *= inv;
    }
    __syncthreads();

    // O = P @ V  (each thread: one (q, 4-dim group))
    for (int idx = tid; idx < 64 * 16; idx += 256) {
        int q = idx >> 4, d4 = idx & 15;
        float4 acc = {0.f, 0.f, 0.f, 0.f};
        int kkend = q + 2 * CTX + 1;
        for (int kk = q; kk < kkend; kk++) {
            float p = Ss[q * S_PAD + kk];
            float4 v = *(const float4*)&Vs[kk * Q_PAD + d4 * 4];
            acc.x += p * v.x; acc.y += p * v.y; acc.z += p * v.z; acc.w += p * v.w;
        }
        *(float4*)(out + ((size_t)(b * TT + q0 + q)) * DIM + h * HD + d4 * 4) = acc;
    }
}

// ---------------- launcher ----------------
extern "C" void kernel_launch(void* const* d_in, const int* in_sizes, int n_in,
                              void* d_out, int out_size)
{
    const float* x       = (const float*)d_in[0];
    const float* norm1_w = (const float*)d_in[1];
    const float* norm2_w = (const float*)d_in[2];
    const float* w_qkv   = (const float*)d_in[3];
    const float* w_out   = (const float*)d_in[4];
    const float* b_out   = (const float*)d_in[5];
    const float* w1      = (const float*)d_in[6];
    const float* b1      = (const float*)d_in[7];
    const float* w2      = (const float*)d_in[8];
    const float* b2      = (const float*)d_in[9];
    float* y = (float*)d_out;

    float *xn, *qkv, *attn, *x1, *hbuf;
    cudaGetSymbolAddress((void**)&xn,   g_xn);
    cudaGetSymbolAddress((void**)&qkv,  g_qkv);
    cudaGetSymbolAddress((void**)&attn, g_attn);
    cudaGetSymbolAddress((void**)&x1,   g_x1);
    cudaGetSymbolAddress((void**)&hbuf, g_h);

    static_assert(SMEM_FLOATS * 4 <= 227 * 1024, "smem");
    cudaFuncSetAttribute(attn_kernel, cudaFuncAttributeMaxDynamicSharedMemorySize,
                         SMEM_FLOATS * 4);

    // 1. rmsnorm(x) -> xn
    rmsnorm_kernel<<<ROWS, 256>>>(x, norm1_w, xn);
    // 2. qkv = xn @ w_qkv
    sgemm_kernel<0><<<dim3((3 * DIM) / 128, ROWS / 128), 256>>>(
        xn, w_qkv, nullptr, nullptr, qkv, ROWS, 3 * DIM, DIM);
    // 3. banded attention -> attn
    attn_kernel<<<dim3(TT / 64, NHEAD, BB), 256, SMEM_FLOATS * 4>>>(qkv, attn);
    // 4. x1 = x + attn @ w_out + b_out
    sgemm_kernel<2><<<dim3(DIM / 128, ROWS / 128), 256>>>(
        attn, w_out, b_out, x, x1, ROWS, DIM, DIM);
    // 5. rmsnorm(x1) -> xn
    rmsnorm_kernel<<<ROWS, 256>>>(x1, norm2_w, xn);
    // 6. h = gelu(xn @ w1 + b1)
    sgemm_kernel<1><<<dim3(FFN / 128, ROWS / 128), 256>>>(
        xn, w1, b1, nullptr, hbuf, ROWS, FFN, DIM);
    // 7. y = x1 + h @ w2 + b2
    sgemm_kernel<2><<<dim3(DIM / 128, ROWS / 128), 256>>>(
        hbuf, w2, b2, x1, y, ROWS, DIM, FFN);
}

// round 3
// speedup vs baseline: 1.4413x; 1.4413x over previous
#include <cuda_runtime.h>
#include <mma.h>
#include <math.h>
#include <stdint.h>

using namespace nvcuda;

#define DIM   512
#define NHEAD 8
#define HD    64
#define FFN   2048
#define BB    4
#define TT    2048
#define ROWS  (BB*TT)     // 8192
#define CTX   64

// ---------------- scratch (allocation-free) ----------------
__device__ float g_xn  [ROWS * DIM];
__device__ float g_qkv [ROWS * 3 * DIM];
__device__ float g_attn[ROWS * DIM];
__device__ float g_x1  [ROWS * DIM];
__device__ float g_h   [ROWS * FFN];
// pre-transposed weights [N, K]
__device__ float g_wqkvT[3 * DIM * DIM];
__device__ float g_woutT[DIM * DIM];
__device__ float g_w1T  [FFN * DIM];
__device__ float g_w2T  [DIM * FFN];

// ================= weight transpose [K,N] -> [N,K] =================
__global__ void transpose_kernel(const float* __restrict__ in, float* __restrict__ out,
                                 int K, int N) {
    __shared__ float tile[32][33];
    int c0 = blockIdx.x * 32, r0 = blockIdx.y * 32;
    int tx = threadIdx.x, ty = threadIdx.y;
    #pragma unroll
    for (int i = 0; i < 32; i += 8)
        tile[ty + i][tx] = in[(size_t)(r0 + ty + i) * N + c0 + tx];
    __syncthreads();
    #pragma unroll
    for (int i = 0; i < 32; i += 8)
        out[(size_t)(c0 + ty + i) * K + r0 + tx] = tile[tx][ty + i];
}

// ================= RMSNorm =================
__global__ void __launch_bounds__(256) rmsnorm_kernel(
    const float* __restrict__ x, const float* __restrict__ w, float* __restrict__ y)
{
    int row = blockIdx.x;
    int t = threadIdx.x;
    const float* xr = x + (size_t)row * DIM;
    float v0 = xr[t], v1 = xr[t + 256];
    float s = v0 * v0 + v1 * v1;
    #pragma unroll
    for (int o = 16; o; o >>= 1) s += __shfl_xor_sync(0xffffffffu, s, o);
    __shared__ float red[8];
    if ((t & 31) == 0) red[t >> 5] = s;
    __syncthreads();
    if (t < 8) {
        float r = red[t];
        #pragma unroll
        for (int o = 4; o; o >>= 1) r += __shfl_xor_sync(0xffu, r, o);
        if (t == 0) red[0] = r;
    }
    __syncthreads();
    float inv = 1.0f / sqrtf(red[0] * (1.0f / DIM) + 1e-6f);
    float* yr = y + (size_t)row * DIM;
    yr[t]       = v0 * inv * w[t];
    yr[t + 256] = v1 * inv * w[t + 256];
}

// ================= wmma tf32 GEMM =================
// C[M,N] = A[M,K] @ Bw^T  with Bw stored [N,K] row-major.
// CTA tile 128x128, 8 warps, warp tile 32x64 (2x4 wmma m16n16k8 tiles).
// K chunks of 32, double-buffered smem.
// EPI: 0 plain, 1 bias+GELU, 2 bias+residual
#define LDA 36
#define LDST 136
#define AB_BYTES  (2 * 128 * LDA * 4)            // 36864 each for A and B
#define GEMM_SMEM (2 * AB_BYTES)                 // 73728; stage (69632) overlaps

template<int EPI>
__global__ void __launch_bounds__(256, 2) gemm_tf32_kernel(
    const float* __restrict__ A, const float* __restrict__ Bw,
    const float* __restrict__ bias, const float* __restrict__ res,
    float* __restrict__ C, int N, int K)
{
    extern __shared__ float sm[];
    float* As = sm;                       // [2][128][LDA]
    float* Bs = sm + 2 * 128 * LDA;       // [2][128][LDA]

    int tid = threadIdx.x;
    int wid = tid >> 5;
    int m0 = blockIdx.y * 128;
    int n0 = blockIdx.x * 128;
    int wm = wid >> 1;      // 0..3  -> 32 rows each
    int wn = wid & 1;       // 0..1  -> 64 cols each

    wmma::fragment<wmma::accumulator, 16, 16, 8, float> acc[2][4];
    #pragma unroll
    for (int i = 0; i < 2; i++)
        #pragma unroll
        for (int j = 0; j < 4; j++)
            wmma::fill_fragment(acc[i][j], 0.0f);

    const int nc = K >> 5;
    int row = tid >> 3, f4 = (tid & 7) * 4;

    // prefetch chunk 0
    float4 av[2][2], bv[2][2];
    #pragma unroll
    for (int h = 0; h < 2; h++) {
        av[0][h] = *(const float4*)(A  + (size_t)(m0 + row + h * 32) * K + f4);
        bv[0][h] = *(const float4*)(Bw + (size_t)(n0 + row + h * 32) * K + f4);
    }

    for (int ic = 0; ic < nc; ic++) {
        int s = ic & 1;
        int cur = ic & 1;          // register set parity
        // store current chunk to smem buffer s (tf32-rounded)
        float* a_s = As + s * 128 * LDA;
        float* b_s = Bs + s * 128 * LDA;
        #pragma unroll
        for (int h = 0; h < 2; h++) {
            int r = row + h * 32;
            float4 a = av[cur][h], b = bv[cur][h];
            a.x = wmma::__float_to_tf32(a.x); a.y = wmma::__float_to_tf32(a.y);
            a.z = wmma::__float_to_tf32(a.z); a.w = wmma::__float_to_tf32(a.w);
            b.x = wmma::__float_to_tf32(b.x); b.y = wmma::__float_to_tf32(b.y);
            b.z = wmma::__float_to_tf32(b.z); b.w = wmma::__float_to_tf32(b.w);
            // rows 0..63 and 64..127 handled by the two halves of thread idx?
            // row in [0,32), h adds 32: covers rows 0..63 -> need 128: use 4 stores
            *(float4*)(a_s + (size_t)r * LDA + f4) = a;
            *(float4*)(b_s + (size_t)r * LDA + f4) = b;
        }
        // second half of rows (64..127)
        #pragma unroll
        for (int h = 0; h < 2; h++) {
            int r = row + 64 + h * 32;
            float4 a = *(const float4*)(A  + (size_t)(m0 + r) * K + ic * 32 + f4);
            float4 b = *(const float4*)(Bw + (size_t)(n0 + r) * K + ic * 32 + f4);
            a.x = wmma::__float_to_tf32(a.x); a.y = wmma::__float_to_tf32(a.y);
            a.z = wmma::__float_to_tf32(a.z); a.w = wmma::__float_to_tf32(a.w);
            b.x = wmma::__float_to_tf32(b.x); b.y = wmma::__float_to_tf32(b.y);
            b.z = wmma::__float_to_tf32(b.z); b.w = wmma::__float_to_tf32(b.w);
            *(float4*)(a_s + (size_t)r * LDA + f4) = a;
            *(float4*)(b_s + (size_t)r * LDA + f4) = b;
        }
        __syncthreads();

        // prefetch next chunk (rows 0..63) while computing
        if (ic + 1 < nc) {
            int nxt = (ic + 1) & 1;
            #pragma unroll
            for (int h = 0; h < 2; h++) {
                av[nxt][h] = *(const float4*)(A  + (size_t)(m0 + row + h * 32) * K + (ic + 1) * 32 + f4);
                bv[nxt][h] = *(const float4*)(Bw + (size_t)(n0 + row + h * 32) * K + (ic + 1) * 32 + f4);
            }
        }

        // compute on buffer s
        #pragma unroll
        for (int ks = 0; ks < 4; ks++) {
            wmma::fragment<wmma::matrix_a, 16, 16, 8, wmma::precision::tf32, wmma::row_major> af[2];
            wmma::fragment<wmma::matrix_b, 16, 16, 8, wmma::precision::tf32, wmma::col_major> bf[4];
            #pragma unroll
            for (int i = 0; i < 2; i++)
                wmma::load_matrix_sync(af[i], a_s + (size_t)(wm * 32 + i * 16) * LDA + ks * 8, LDA);
            #pragma unroll
            for (int j = 0; j < 4; j++)
                wmma::load_matrix_sync(bf[j], b_s + (size_t)(wn * 64 + j * 16) * LDA + ks * 8, LDA);
            #pragma unroll
            for (int i = 0; i < 2; i++)
                #pragma unroll
                for (int j = 0; j < 4; j++)
                    wmma::mma_sync(acc[i][j], af[i], bf[j], acc[i][j]);
        }
        __syncthreads();
    }

    // ---- epilogue: acc -> smem stage -> coalesced fused STG ----
    float* stage = sm;   // [128][LDST]
    #pragma unroll
    for (int i = 0; i < 2; i++)
        #pragma unroll
        for (int j = 0; j < 4; j++)
            wmma::store_matrix_sync(stage + (size_t)(wm * 32 + i * 16) * LDST + wn * 64 + j * 16,
                                    acc[i][j], LDST, wmma::mem_row_major);
    __syncthreads();

    #pragma unroll
    for (int jj = 0; jj < 16; jj++) {
        int idx = jj * 256 + tid;
        int m = idx >> 5, g = idx & 31;
        float4 v = *(float4*)(stage + (size_t)m * LDST + g * 4);
        int c = n0 + g * 4;
        if (EPI == 1) {
            float4 b = *(const float4*)(bias + c);
            v.x += b.x; v.y += b.y; v.z += b.z; v.w += b.w;
            v.x = 0.5f * v.x * (1.0f + erff(v.x * 0.70710678118654752f));
            v.y = 0.5f * v.y * (1.0f + erff(v.y * 0.70710678118654752f));
            v.z = 0.5f * v.z * (1.0f + erff(v.z * 0.70710678118654752f));
            v.w = 0.5f * v.w * (1.0f + erff(v.w * 0.70710678118654752f));
        } else if (EPI == 2) {
            float4 b = *(const float4*)(bias + c);
            float4 rr = *(const float4*)(res + (size_t)(m0 + m) * N + c);
            v.x += b.x + rr.x; v.y += b.y + rr.y;
            v.z += b.z + rr.z; v.w += b.w + rr.w;
        }
        *(float4*)(C + (size_t)(m0 + m) * N + c) = v;
    }
}

// ================= Banded attention (fp32) =================
#define Q_PAD 68
#define S_PAD 193
#define SMEM_FLOATS (64*Q_PAD + 192*Q_PAD + 192*Q_PAD + 64*S_PAD)

__global__ void __launch_bounds__(256) attn_kernel(
    const float* __restrict__ qkv, float* __restrict__ out)
{
    extern __shared__ float sm[];
    float* Qs = sm;
    float* Ks = Qs + 64 * Q_PAD;
    float* Vs = Ks + 192 * Q_PAD;
    float* Ss = Vs + 192 * Q_PAD;

    int tid = threadIdx.x;
    int qt = blockIdx.x, h = blockIdx.y, b = blockIdx.z;
    int q0 = qt * 64;
    int kbase = q0 - CTX;

    for (int idx = tid; idx < 64 * 16; idx += 256) {
        int r = idx >> 4, d4 = idx & 15;
        float4 v = *(const float4*)(qkv + ((size_t)(b * TT + q0 + r)) * (3 * DIM) + h * HD + d4 * 4);
        *(float4*)&Qs[r * Q_PAD + d4 * 4] = v;
    }
    for (int idx = tid; idx < 192 * 16; idx += 256) {
        int r = idx >> 4, d4 = idx & 15;
        int kg = kbase + r;
        float4 kv = {0.f, 0.f, 0.f, 0.f}, vv = {0.f, 0.f, 0.f, 0.f};
        if (kg >= 0 && kg < TT) {
            const float* base = qkv + ((size_t)(b * TT + kg)) * (3 * DIM) + h * HD + d4 * 4;
            kv = *(const float4*)(base + DIM);
            vv = *(const float4*)(base + 2 * DIM);
        }
        *(float4*)&Ks[r * Q_PAD + d4 * 4] = kv;
        *(float4*)&Vs[r * Q_PAD + d4 * 4] = vv;
    }
    __syncthreads();

    const float scale = 0.125f;
    for (int idx = tid; idx < 64 * 192; idx += 256) {
        int q = idx / 192, kk = idx - q * 192;
        int kg = kbase + kk;
        float s = -1e30f;
        if (kk >= q && kk <= q + 2 * CTX && kg >= 0 && kg < TT) {
            const float4* qp = (const float4*)&Qs[q * Q_PAD];
            const float4* kp = (const float4*)&Ks[kk * Q_PAD];
            float a0 = 0.f;
            #pragma unroll
            for (int d = 0; d < 16; d++) {
                float4 a = qp[d], c = kp[d];
                a0 += a.x * c.x + a.y * c.y + a.z * c.z + a.w * c.w;
            }
            s = a0 * scale;
        }
        Ss[q * S_PAD + kk] = s;
    }
    __syncthreads();

    {
        int q = tid >> 2, l = tid & 3;
        float mx = -1e30f;
        for (int kk = l; kk < 192; kk += 4) mx = fmaxf(mx, Ss[q * S_PAD + kk]);
        mx = fmaxf(mx, __shfl_xor_sync(0xffffffffu, mx, 1));
        mx = fmaxf(mx, __shfl_xor_sync(0xffffffffu, mx, 2));
        float sum = 0.f;
        for (int kk = l; kk < 192; kk += 4) {
            float s = Ss[q * S_PAD + kk];
            float e = (s > -1e29f) ? expf(s - mx) : 0.f;
            Ss[q * S_PAD + kk] = e;
            sum += e;
        }
        sum += __shfl_xor_sync(0xffffffffu, sum, 1);
        sum += __shfl_xor_sync(0xffffffffu, sum, 2);
        float inv = 1.f / sum;
        for (int kk = l; kk < 192; kk += 4) Ss[q * S_PAD + kk] *= inv;
    }
    __syncthreads();

    for (int idx = tid; idx < 64 * 16; idx += 256) {
        int q = idx >> 4, d4 = idx & 15;
        float4 acc = {0.f, 0.f, 0.f, 0.f};
        int kkend = q + 2 * CTX + 1;
        for (int kk = q; kk < kkend; kk++) {
            float p = Ss[q * S_PAD + kk];
            float4 v = *(const float4*)&Vs[kk * Q_PAD + d4 * 4];
            acc.x += p * v.x; acc.y += p * v.y; acc.z += p * v.z; acc.w += p * v.w;
        }
        *(float4*)(out + ((size_t)(b * TT + q0 + q)) * DIM + h * HD + d4 * 4) = acc;
    }
}

// ================= launcher =================
extern "C" void kernel_launch(void* const* d_in, const int* in_sizes, int n_in,
                              void* d_out, int out_size)
{
    const float* x       = (const float*)d_in[0];
    const float* norm1_w = (const float*)d_in[1];
    const float* norm2_w = (const float*)d_in[2];
    const float* w_qkv   = (const float*)d_in[3];
    const float* w_out   = (const float*)d_in[4];
    const float* b_out   = (const float*)d_in[5];
    const float* w1      = (const float*)d_in[6];
    const float* b1      = (const float*)d_in[7];
    const float* w2      = (const float*)d_in[8];
    const float* b2      = (const float*)d_in[9];
    float* y = (float*)d_out;

    float *xn, *qkv, *attn, *x1, *hbuf, *wqkvT, *woutT, *w1T, *w2T;
    cudaGetSymbolAddress((void**)&xn,    g_xn);
    cudaGetSymbolAddress((void**)&qkv,   g_qkv);
    cudaGetSymbolAddress((void**)&attn,  g_attn);
    cudaGetSymbolAddress((void**)&x1,    g_x1);
    cudaGetSymbolAddress((void**)&hbuf,  g_h);
    cudaGetSymbolAddress((void**)&wqkvT, g_wqkvT);
    cudaGetSymbolAddress((void**)&woutT, g_woutT);
    cudaGetSymbolAddress((void**)&w1T,   g_w1T);
    cudaGetSymbolAddress((void**)&w2T,   g_w2T);

    static_assert(SMEM_FLOATS * 4 <= 227 * 1024, "smem");
    cudaFuncSetAttribute(attn_kernel, cudaFuncAttributeMaxDynamicSharedMemorySize,
                         SMEM_FLOATS * 4);
    cudaFuncSetAttribute(gemm_tf32_kernel<0>, cudaFuncAttributeMaxDynamicSharedMemorySize, GEMM_SMEM);
    cudaFuncSetAttribute(gemm_tf32_kernel<1>, cudaFuncAttributeMaxDynamicSharedMemorySize, GEMM_SMEM);
    cudaFuncSetAttribute(gemm_tf32_kernel<2>, cudaFuncAttributeMaxDynamicSharedMemorySize, GEMM_SMEM);

    // 0. transpose weights to [N, K]
    transpose_kernel<<<dim3((3 * DIM) / 32, DIM / 32), dim3(32, 8)>>>(w_qkv, wqkvT, DIM, 3 * DIM);
    transpose_kernel<<<dim3(DIM / 32, DIM / 32),       dim3(32, 8)>>>(w_out, woutT, DIM, DIM);
    transpose_kernel<<<dim3(FFN / 32, DIM / 32),       dim3(32, 8)>>>(w1, w1T, DIM, FFN);
    transpose_kernel<<<dim3(DIM / 32, FFN / 32),       dim3(32, 8)>>>(w2, w2T, FFN, DIM);

    // 1. rmsnorm(x) -> xn
    rmsnorm_kernel<<<ROWS, 256>>>(x, norm1_w, xn);
    // 2. qkv = xn @ w_qkv
    gemm_tf32_kernel<0><<<dim3((3 * DIM) / 128, ROWS / 128), 256, GEMM_SMEM>>>(
        xn, wqkvT, nullptr, nullptr, qkv, 3 * DIM, DIM);
    // 3. banded attention
    attn_kernel<<<dim3(TT / 64, NHEAD, BB), 256, SMEM_FLOATS * 4>>>(qkv, attn);
    // 4. x1 = x + attn @ w_out + b_out
    gemm_tf32_kernel<2><<<dim3(DIM / 128, ROWS / 128), 256, GEMM_SMEM>>>(
        attn, woutT, b_out, x, x1, DIM, DIM);
    // 5. rmsnorm(x1) -> xn
    rmsnorm_kernel<<<ROWS, 256>>>(x1, norm2_w, xn);
    // 6. h = gelu(xn @ w1 + b1)
    gemm_tf32_kernel<1><<<dim3(FFN / 128, ROWS / 128), 256, GEMM_SMEM>>>(
        xn, w1T, b1, nullptr, hbuf, FFN, DIM);
    // 7. y = x1 + h @ w2 + b2
    gemm_tf32_kernel<2><<<dim3(DIM / 128, ROWS / 128), 256, GEMM_SMEM>>>(
        hbuf, w2T, b2, x1, y, DIM, FFN);
}

// round 4
// speedup vs baseline: 1.5238x; 1.0572x over previous
#include <cuda_runtime.h>
#include <mma.h>
#include <math.h>
#include <stdint.h>

using namespace nvcuda;

#define DIM   512
#define NHEAD 8
#define HD    64
#define FFN   2048
#define BB    4
#define TT    2048
#define ROWS  (BB*TT)     // 8192
#define CTX   64

// ---------------- scratch (allocation-free) ----------------
__device__ float g_xn  [ROWS * DIM];
__device__ float g_qkv [ROWS * 3 * DIM];
__device__ float g_attn[ROWS * DIM];
__device__ float g_x1  [ROWS * DIM];
__device__ float g_h   [ROWS * FFN];

// ================= cp.async helpers =================
__device__ __forceinline__ uint32_t smem_u32(const void* p) {
    uint32_t a;
    asm("{ .reg .u64 t; cvta.to.shared.u64 t, %1; cvt.u32.u64 %0, t; }" : "=r"(a) : "l"(p));
    return a;
}
__device__ __forceinline__ void cp_async16(uint32_t saddr, const void* gaddr) {
    asm volatile("cp.async.cg.shared.global [%0], [%1], 16;" :: "r"(saddr), "l"(gaddr));
}
#define CP_COMMIT() asm volatile("cp.async.commit_group;" ::: "memory")
#define CP_WAIT(n)  asm volatile("cp.async.wait_group %0;" :: "n"(n) : "memory")

// ================= RMSNorm =================
__global__ void __launch_bounds__(256) rmsnorm_kernel(
    const float* __restrict__ x, const float* __restrict__ w, float* __restrict__ y)
{
    int row = blockIdx.x;
    int t = threadIdx.x;
    const float* xr = x + (size_t)row * DIM;
    float v0 = xr[t], v1 = xr[t + 256];
    float s = v0 * v0 + v1 * v1;
    #pragma unroll
    for (int o = 16; o; o >>= 1) s += __shfl_xor_sync(0xffffffffu, s, o);
    __shared__ float red[8];
    if ((t & 31) == 0) red[t >> 5] = s;
    __syncthreads();
    if (t < 8) {
        float r = red[t];
        #pragma unroll
        for (int o = 4; o; o >>= 1) r += __shfl_xor_sync(0xffu, r, o);
        if (t == 0) red[0] = r;
    }
    __syncthreads();
    float inv = 1.0f / sqrtf(red[0] * (1.0f / DIM) + 1e-6f);
    float* yr = y + (size_t)row * DIM;
    yr[t]       = v0 * inv * w[t];
    yr[t + 256] = v1 * inv * w[t + 256];
}

// ================= wmma tf32 GEMM, cp.async pipelined =================
// C[M,N] = A[M,K] @ B[K,N], both row-major. CTA tile 128x128, 4 warps
// (warp tile 64x64 = 4x4 wmma m16n16k8). K chunks of 32, 3-stage cp.async.
// EPI: 0 plain, 1 bias+GELU, 2 bias+residual
#define KC      32
#define LDA     36
#define LDB     132
#define STAGES  3
#define A_STG   (128 * LDA)          // floats
#define B_STG   (KC * LDB)
#define STG_FL  (A_STG + B_STG)      // 8832 floats = 35328 B
#define LDST    136
#define GEMM_SMEM (STAGES * STG_FL * 4)   // 105984 B

template<int EPI>
__global__ void __launch_bounds__(128, 2) gemm_tf32_kernel(
    const float* __restrict__ A, const float* __restrict__ Bg,
    const float* __restrict__ bias, const float* __restrict__ res,
    float* __restrict__ C, int N, int K)
{
    extern __shared__ float sm[];
    uint32_t sm_base = smem_u32(sm);

    int tid = threadIdx.x;
    int wid = tid >> 5;
    int m0 = blockIdx.y * 128;
    int n0 = blockIdx.x * 128;
    int wm = wid >> 1;      // 0..1 -> 64 rows
    int wn = wid & 1;       // 0..1 -> 64 cols

    const int nc = K / KC;

    // per-thread copy tasks: A 128x32 (8 f4-segs/row), B 32x128 (32 segs/row)
    int a_row = tid >> 0;           // reuse below
    // A: 1024 tasks = tid + i*128, i<8 : row=task>>3, seg=task&7
    // B: 1024 tasks = tid + i*128, i<8 : row=task>>5, seg=task&31

    auto issue_chunk = [&](int ic) {
        float* As = sm + (ic % STAGES) * STG_FL;
        float* Bs = As + A_STG;
        uint32_t as_addr = sm_base + (uint32_t)((ic % STAGES) * STG_FL) * 4;
        uint32_t bs_addr = as_addr + A_STG * 4;
        #pragma unroll
        for (int i = 0; i < 8; i++) {
            int task = tid + i * 128;
            int r = task >> 3, sg = task & 7;
            cp_async16(as_addr + (uint32_t)(r * LDA + sg * 4) * 4,
                       A + (size_t)(m0 + r) * K + ic * KC + sg * 4);
        }
        #pragma unroll
        for (int i = 0; i < 8; i++) {
            int task = tid + i * 128;
            int r = task >> 5, sg = task & 31;
            cp_async16(bs_addr + (uint32_t)(r * LDB + sg * 4) * 4,
                       Bg + (size_t)(ic * KC + r) * N + n0 + sg * 4);
        }
    };

    wmma::fragment<wmma::accumulator, 16, 16, 8, float> acc[4][4];
    #pragma unroll
    for (int i = 0; i < 4; i++)
        #pragma unroll
        for (int j = 0; j < 4; j++)
            wmma::fill_fragment(acc[i][j], 0.0f);

    // prologue
    issue_chunk(0); CP_COMMIT();
    issue_chunk(1); CP_COMMIT();

    for (int ic = 0; ic < nc; ic++) {
        CP_WAIT(STAGES - 2);
        __syncthreads();
        if (ic + STAGES - 1 < nc) issue_chunk(ic + STAGES - 1);
        CP_COMMIT();

        float* As = sm + (ic % STAGES) * STG_FL;
        float* Bs = As + A_STG;
        #pragma unroll
        for (int ks = 0; ks < 4; ks++) {
            wmma::fragment<wmma::matrix_a, 16, 16, 8, wmma::precision::tf32, wmma::row_major> af[4];
            wmma::fragment<wmma::matrix_b, 16, 16, 8, wmma::precision::tf32, wmma::row_major> bf[4];
            #pragma unroll
            for (int i = 0; i < 4; i++) {
                wmma::load_matrix_sync(af[i], As + (size_t)(wm * 64 + i * 16) * LDA + ks * 8, LDA);
                #pragma unroll
                for (int t = 0; t < af[i].num_elements; t++)
                    af[i].x[t] = wmma::__float_to_tf32(af[i].x[t]);
            }
            #pragma unroll
            for (int j = 0; j < 4; j++) {
                wmma::load_matrix_sync(bf[j], Bs + (size_t)(ks * 8) * LDB + wn * 64 + j * 16, LDB);
                #pragma unroll
                for (int t = 0; t < bf[j].num_elements; t++)
                    bf[j].x[t] = wmma::__float_to_tf32(bf[j].x[t]);
            }
            #pragma unroll
            for (int i = 0; i < 4; i++)
                #pragma unroll
                for (int j = 0; j < 4; j++)
                    wmma::mma_sync(acc[i][j], af[i], bf[j], acc[i][j]);
        }
    }

    // ---- epilogue: acc -> smem stage -> coalesced fused STG ----
    __syncthreads();
    float* stage = sm;   // [128][LDST]
    #pragma unroll
    for (int i = 0; i < 4; i++)
        #pragma unroll
        for (int j = 0; j < 4; j++)
            wmma::store_matrix_sync(stage + (size_t)(wm * 64 + i * 16) * LDST + wn * 64 + j * 16,
                                    acc[i][j], LDST, wmma::mem_row_major);
    __syncthreads();

    #pragma unroll
    for (int jj = 0; jj < 32; jj++) {
        int idx = jj * 128 + tid;
        int m = idx >> 5, g = idx & 31;
        float4 v = *(float4*)(stage + (size_t)m * LDST + g * 4);
        int c = n0 + g * 4;
        if (EPI == 1) {
            float4 b = *(const float4*)(bias + c);
            v.x += b.x; v.y += b.y; v.z += b.z; v.w += b.w;
            v.x = 0.5f * v.x * (1.0f + erff(v.x * 0.70710678118654752f));
            v.y = 0.5f * v.y * (1.0f + erff(v.y * 0.70710678118654752f));
            v.z = 0.5f * v.z * (1.0f + erff(v.z * 0.70710678118654752f));
            v.w = 0.5f * v.w * (1.0f + erff(v.w * 0.70710678118654752f));
        } else if (EPI == 2) {
            float4 b = *(const float4*)(bias + c);
            float4 rr = *(const float4*)(res + (size_t)(m0 + m) * N + c);
            v.x += b.x + rr.x; v.y += b.y + rr.y;
            v.z += b.z + rr.z; v.w += b.w + rr.w;
        }
        *(float4*)(C + (size_t)(m0 + m) * N + c) = v;
    }
}

// ================= Banded attention (fp32) =================
#define Q_PAD 68
#define S_PAD 193
#define SMEM_FLOATS (64*Q_PAD + 192*Q_PAD + 192*Q_PAD + 64*S_PAD)

__global__ void __launch_bounds__(256) attn_kernel(
    const float* __restrict__ qkv, float* __restrict__ out)
{
    extern __shared__ float sm[];
    float* Qs = sm;
    float* Ks = Qs + 64 * Q_PAD;
    float* Vs = Ks + 192 * Q_PAD;
    float* Ss = Vs + 192 * Q_PAD;

    int tid = threadIdx.x;
    int qt = blockIdx.x, h = blockIdx.y, b = blockIdx.z;
    int q0 = qt * 64;
    int kbase = q0 - CTX;

    for (int idx = tid; idx < 64 * 16; idx += 256) {
        int r = idx >> 4, d4 = idx & 15;
        float4 v = *(const float4*)(qkv + ((size_t)(b * TT + q0 + r)) * (3 * DIM) + h * HD + d4 * 4);
        *(float4*)&Qs[r * Q_PAD + d4 * 4] = v;
    }
    for (int idx = tid; idx < 192 * 16; idx += 256) {
        int r = idx >> 4, d4 = idx & 15;
        int kg = kbase + r;
        float4 kv = {0.f, 0.f, 0.f, 0.f}, vv = {0.f, 0.f, 0.f, 0.f};
        if (kg >= 0 && kg < TT) {
            const float* base = qkv + ((size_t)(b * TT + kg)) * (3 * DIM) + h * HD + d4 * 4;
            kv = *(const float4*)(base + DIM);
            vv = *(const float4*)(base + 2 * DIM);
        }
        *(float4*)&Ks[r * Q_PAD + d4 * 4] = kv;
        *(float4*)&Vs[r * Q_PAD + d4 * 4] = vv;
    }
    __syncthreads();

    const float scale = 0.125f;
    for (int idx = tid; idx < 64 * 192; idx += 256) {
        int q = idx / 192, kk = idx - q * 192;
        int kg = kbase + kk;
        float s = -1e30f;
        if (kk >= q && kk <= q + 2 * CTX && kg >= 0 && kg < TT) {
            const float4* qp = (const float4*)&Qs[q * Q_PAD];
            const float4* kp = (const float4*)&Ks[kk * Q_PAD];
            float a0 = 0.f;
            #pragma unroll
            for (int d = 0; d < 16; d++) {
                float4 a = qp[d], c = kp[d];
                a0 += a.x * c.x + a.y * c.y + a.z * c.z + a.w * c.w;
            }
            s = a0 * scale;
        }
        Ss[q * S_PAD + kk] = s;
    }
    __syncthreads();

    {
        int q = tid >> 2, l = tid & 3;
        float mx = -1e30f;
        for (int kk = l; kk < 192; kk += 4) mx = fmaxf(mx, Ss[q * S_PAD + kk]);
        mx = fmaxf(mx, __shfl_xor_sync(0xffffffffu, mx, 1));
        mx = fmaxf(mx, __shfl_xor_sync(0xffffffffu, mx, 2));
        float sum = 0.f;
        for (int kk = l; kk < 192; kk += 4) {
            float s = Ss[q * S_PAD + kk];
            float e = (s > -1e29f) ? expf(s - mx) : 0.f;
            Ss[q * S_PAD + kk] = e;
            sum += e;
        }
        sum += __shfl_xor_sync(0xffffffffu, sum, 1);
        sum += __shfl_xor_sync(0xffffffffu, sum, 2);
        float inv = 1.f / sum;
        for (int kk = l; kk < 192; kk += 4) Ss[q * S_PAD + kk] *= inv;
    }
    __syncthreads();

    for (int idx = tid; idx < 64 * 16; idx += 256) {
        int q = idx >> 4, d4 = idx & 15;
        float4 acc = {0.f, 0.f, 0.f, 0.f};
        int kkend = q + 2 * CTX + 1;
        for (int kk = q; kk < kkend; kk++) {
            float p = Ss[q * S_PAD + kk];
            float4 v = *(const float4*)&Vs[kk * Q_PAD + d4 * 4];
            acc.x += p * v.x; acc.y += p * v.y; acc.z += p * v.z; acc.w += p * v.w;
        }
        *(float4*)(out + ((size_t)(b * TT + q0 + q)) * DIM + h * HD + d4 * 4) = acc;
    }
}

// ================= launcher =================
extern "C" void kernel_launch(void* const* d_in, const int* in_sizes, int n_in,
                              void* d_out, int out_size)
{
    const float* x       = (const float*)d_in[0];
    const float* norm1_w = (const float*)d_in[1];
    const float* norm2_w = (const float*)d_in[2];
    const float* w_qkv   = (const float*)d_in[3];
    const float* w_out   = (const float*)d_in[4];
    const float* b_out   = (const float*)d_in[5];
    const float* w1      = (const float*)d_in[6];
    const float* b1      = (const float*)d_in[7];
    const float* w2      = (const float*)d_in[8];
    const float* b2      = (const float*)d_in[9];
    float* y = (float*)d_out;

    float *xn, *qkv, *attn, *x1, *hbuf;
    cudaGetSymbolAddress((void**)&xn,   g_xn);
    cudaGetSymbolAddress((void**)&qkv,  g_qkv);
    cudaGetSymbolAddress((void**)&attn, g_attn);
    cudaGetSymbolAddress((void**)&x1,   g_x1);
    cudaGetSymbolAddress((void**)&hbuf, g_h);

    static_assert(SMEM_FLOATS * 4 <= 227 * 1024, "smem");
    cudaFuncSetAttribute(attn_kernel, cudaFuncAttributeMaxDynamicSharedMemorySize,
                         SMEM_FLOATS * 4);
    cudaFuncSetAttribute(gemm_tf32_kernel<0>, cudaFuncAttributeMaxDynamicSharedMemorySize, GEMM_SMEM);
    cudaFuncSetAttribute(gemm_tf32_kernel<1>, cudaFuncAttributeMaxDynamicSharedMemorySize, GEMM_SMEM);
    cudaFuncSetAttribute(gemm_tf32_kernel<2>, cudaFuncAttributeMaxDynamicSharedMemorySize, GEMM_SMEM);

    // 1. rmsnorm(x) -> xn
    rmsnorm_kernel<<<ROWS, 256>>>(x, norm1_w, xn);
    // 2. qkv = xn @ w_qkv
    gemm_tf32_kernel<0><<<dim3((3 * DIM) / 128, ROWS / 128), 128, GEMM_SMEM>>>(
        xn, w_qkv, nullptr, nullptr, qkv, 3 * DIM, DIM);
    // 3. banded attention
    attn_kernel<<<dim3(TT / 64, NHEAD, BB), 256, SMEM_FLOATS * 4>>>(qkv, attn);
    // 4. x1 = x + attn @ w_out + b_out
    gemm_tf32_kernel<2><<<dim3(DIM / 128, ROWS / 128), 128, GEMM_SMEM>>>(
        attn, w_out, b_out, x, x1, DIM, DIM);
    // 5. rmsnorm(x1) -> xn
    rmsnorm_kernel<<<ROWS, 256>>>(x1, norm2_w, xn);
    // 6. h = gelu(xn @ w1 + b1)
    gemm_tf32_kernel<1><<<dim3(FFN / 128, ROWS / 128), 128, GEMM_SMEM>>>(
        xn, w1, b1, nullptr, hbuf, FFN, DIM);
    // 7. y = x1 + h @ w2 + b2
    gemm_tf32_kernel<2><<<dim3(DIM / 128, ROWS / 128), 128, GEMM_SMEM>>>(
        hbuf, w2, b2, x1, y, DIM, FFN);
}